// round 1
// baseline (speedup 1.0000x reference)
#include <cuda_runtime.h>
#include <stdint.h>

#define BB 16
#define CC 19
#define HH 512
#define WW 512
#define KX 4
#define WSEG 4            // 512 / (32*KX)
#define HCH 4
#define HROWS (HH/HCH)    // 128
#define WPB 8             // warps per block
#define NWARPS (BB*CC*WSEG*HCH)   // 4864
#define NBLOCKS (NWARPS/WPB)      // 608

__device__ unsigned char g_tgt8[BB*HH*WW];  // 4 MB scratch (static, allowed)
__device__ double g_acc;
__device__ int g_is32;

// ---------------------------------------------------------------------------
// Detect target element width (int64 vs silently-demoted int32) + zero acc.
// If int64: high 32-bit words are all zero (values in [0,19)).
// ---------------------------------------------------------------------------
__global__ void detect_kernel(const unsigned int* __restrict__ t) {
    __shared__ int f;
    if (threadIdx.x == 0) f = 0;
    __syncthreads();
    for (int i = threadIdx.x; i < 4096; i += blockDim.x)
        if (t[2 * i + 1] != 0u) f = 1;
    __syncthreads();
    if (threadIdx.x == 0) { g_is32 = f; g_acc = 0.0; }
}

// ---------------------------------------------------------------------------
// Convert targets -> uint8 (stays L2-resident for the 19x channel reuse).
// ---------------------------------------------------------------------------
__global__ void prep_kernel(const unsigned int* __restrict__ t) {
    const int n4 = BB * HH * WW / 4;
    const bool is32 = (g_is32 != 0);
    for (int i = blockIdx.x * blockDim.x + threadIdx.x; i < n4;
         i += gridDim.x * blockDim.x) {
        uchar4 o;
        if (is32) {
            uint4 v = reinterpret_cast<const uint4*>(t)[i];
            o.x = (unsigned char)v.x; o.y = (unsigned char)v.y;
            o.z = (unsigned char)v.z; o.w = (unsigned char)v.w;
        } else {
            o.x = (unsigned char)t[(4 * i + 0) * 2];
            o.y = (unsigned char)t[(4 * i + 1) * 2];
            o.z = (unsigned char)t[(4 * i + 2) * 2];
            o.w = (unsigned char)t[(4 * i + 3) * 2];
        }
        reinterpret_cast<uchar4*>(g_tgt8)[i] = o;
    }
}

// ---------------------------------------------------------------------------
// Main fused kernel: separable sliding-window Sobel on inputs AND on the
// implicit one-hot(targets), squared-diff accumulated on the fly.
// One warp = one (b, c, w-segment, h-chunk) strip; each lane owns 4 pixels.
// ---------------------------------------------------------------------------
struct RowD { float a[KX], s[KX], u[KX], v[KX]; };

__device__ __forceinline__ void compute_row(
    RowD& r, const float* __restrict__ plane,
    const unsigned char* __restrict__ tplane,
    int row, int w0, int lane, int cc)
{
    if (row < 0 || row >= HH) {
        #pragma unroll
        for (int i = 0; i < KX; i++) { r.a[i]=0.f; r.s[i]=0.f; r.u[i]=0.f; r.v[i]=0.f; }
        return;
    }
    const float* xr = plane + (size_t)row * WW;
    float4 xv = *reinterpret_cast<const float4*>(xr + w0);
    float xl = __shfl_up_sync(0xffffffffu, xv.w, 1);
    float xrt = __shfl_down_sync(0xffffffffu, xv.x, 1);
    if (lane == 0)  xl  = (w0 > 0)        ? __ldg(xr + w0 - 1)  : 0.f;
    if (lane == 31) xrt = (w0 + KX < WW)  ? __ldg(xr + w0 + KX) : 0.f;
    // diff-x
    r.a[0] = xv.y - xl;   r.a[1] = xv.z - xv.x;
    r.a[2] = xv.w - xv.y; r.a[3] = xrt  - xv.z;
    // smooth-x
    r.s[0] = fmaf(2.f, xv.x, xl   + xv.y);
    r.s[1] = fmaf(2.f, xv.y, xv.x + xv.z);
    r.s[2] = fmaf(2.f, xv.z, xv.y + xv.w);
    r.s[3] = fmaf(2.f, xv.w, xv.z + xrt);

    const unsigned char* trow = tplane + (size_t)row * WW;
    uchar4 t4 = *reinterpret_cast<const uchar4*>(trow + w0);
    float m0 = (t4.x == cc) ? 1.f : 0.f;
    float m1 = (t4.y == cc) ? 1.f : 0.f;
    float m2 = (t4.z == cc) ? 1.f : 0.f;
    float m3 = (t4.w == cc) ? 1.f : 0.f;
    float ml = __shfl_up_sync(0xffffffffu, m3, 1);
    float mr = __shfl_down_sync(0xffffffffu, m0, 1);
    if (lane == 0)  ml = (w0 > 0       && trow[w0 - 1]  == cc) ? 1.f : 0.f;
    if (lane == 31) mr = (w0 + KX < WW && trow[w0 + KX] == cc) ? 1.f : 0.f;
    r.u[0] = m1 - ml; r.u[1] = m2 - m0; r.u[2] = m3 - m1; r.u[3] = mr - m2;
    r.v[0] = fmaf(2.f, m0, ml + m1);
    r.v[1] = fmaf(2.f, m1, m0 + m2);
    r.v[2] = fmaf(2.f, m2, m1 + m3);
    r.v[3] = fmaf(2.f, m3, m2 + mr);
}

__device__ __forceinline__ void emit_row(
    const RowD& P, const RowD& C0, const RowD& N, float& acc)
{
    #pragma unroll
    for (int i = 0; i < KX; i++) {
        float gx  = fmaf(2.f, C0.a[i], P.a[i] + N.a[i]);
        float gy  = N.s[i] - P.s[i];
        float ein = fabsf(gx) + fabsf(gy);
        float gxt = fmaf(2.f, C0.u[i], P.u[i] + N.u[i]);
        float gyt = N.v[i] - P.v[i];
        float etg = fabsf(gxt) + fabsf(gyt);
        float d = ein - etg;
        acc = fmaf(d, d, acc);
    }
}

__global__ __launch_bounds__(WPB * 32, 2)
void edge_kernel(const float* __restrict__ inp)
{
    const int warp = blockIdx.x * WPB + (threadIdx.x >> 5);
    const int lane = threadIdx.x & 31;

    const int wseg = warp & (WSEG - 1);
    const int hch  = (warp >> 2) & (HCH - 1);
    const int t2   = warp >> 4;          // = b*CC + c, in [0, 304)
    const int c    = t2 % CC;
    const int b    = t2 / CC;

    const int w0 = wseg * (32 * KX) + lane * KX;
    const int h0 = hch * HROWS;
    const float* plane = inp + ((size_t)(b * CC + c)) * HH * WW;
    const unsigned char* tplane = g_tgt8 + (size_t)b * HH * WW;

    float acc = 0.f;
    RowD rA, rB, rC;
    compute_row(rA, plane, tplane, h0 - 1, w0, lane, c);
    compute_row(rB, plane, tplane, h0,     w0, lane, c);

    int y = h0;
    // 42 triples = 126 output rows, then 2 remainder rows (128 total)
    #pragma unroll 1
    for (int it = 0; it < HROWS / 3; ++it) {
        compute_row(rC, plane, tplane, y + 1, w0, lane, c); emit_row(rA, rB, rC, acc); ++y;
        compute_row(rA, plane, tplane, y + 1, w0, lane, c); emit_row(rB, rC, rA, acc); ++y;
        compute_row(rB, plane, tplane, y + 1, w0, lane, c); emit_row(rC, rA, rB, acc); ++y;
    }
    compute_row(rC, plane, tplane, y + 1, w0, lane, c); emit_row(rA, rB, rC, acc); ++y;
    compute_row(rA, plane, tplane, y + 1, w0, lane, c); emit_row(rB, rC, rA, acc);

    // reduce: warp -> block -> global double
    #pragma unroll
    for (int o = 16; o; o >>= 1) acc += __shfl_xor_sync(0xffffffffu, acc, o);
    __shared__ float ws[WPB];
    if (lane == 0) ws[threadIdx.x >> 5] = acc;
    __syncthreads();
    if (threadIdx.x == 0) {
        double s = 0.0;
        #pragma unroll
        for (int i = 0; i < WPB; i++) s += (double)ws[i];
        atomicAdd(&g_acc, s);
    }
}

__global__ void fin_kernel(float* __restrict__ out) {
    out[0] = (float)(g_acc * (1.0 / ((double)BB * HH * WW)));
}

// ---------------------------------------------------------------------------
extern "C" void kernel_launch(void* const* d_in, const int* in_sizes, int n_in,
                              void* d_out, int out_size)
{
    // Resolve order defensively: inputs has 79,691,776 elems, targets 4,194,304.
    const float* inp;
    const unsigned int* tgt;
    if (in_sizes[0] == BB * CC * HH * WW) {
        inp = (const float*)d_in[0];
        tgt = (const unsigned int*)d_in[1];
    } else {
        inp = (const float*)d_in[1];
        tgt = (const unsigned int*)d_in[0];
    }
    float* out = (float*)d_out;

    detect_kernel<<<1, 1024>>>(tgt);
    prep_kernel<<<4096, 256>>>(tgt);
    edge_kernel<<<NBLOCKS, WPB * 32>>>(inp);
    fin_kernel<<<1, 1>>>(out);
}

// round 2
// speedup vs baseline: 1.4091x; 1.4091x over previous
#include <cuda_runtime.h>
#include <stdint.h>

#define BB 16
#define CC 19
#define HH 512
#define WW 512
#define KX 4
#define WSEG 4            // 512 / (32*KX)
#define HCH 8
#define HROWS (HH/HCH)    // 64
#define WPB 4             // warps per block (128 threads)
#define NWARPS (BB*CC*WSEG*HCH)   // 9728
#define NBLOCKS (NWARPS/WPB)      // 2432

__device__ unsigned char g_tgt8[BB*HH*WW];  // 4 MB scratch (static, allowed)
__device__ double g_acc;
__device__ int g_is32;

// ---------------------------------------------------------------------------
// Detect target element width (int64 vs silently-demoted int32) + zero acc.
// ---------------------------------------------------------------------------
__global__ void detect_kernel(const unsigned int* __restrict__ t) {
    __shared__ int f;
    if (threadIdx.x == 0) f = 0;
    __syncthreads();
    for (int i = threadIdx.x; i < 4096; i += blockDim.x)
        if (t[2 * i + 1] != 0u) f = 1;
    __syncthreads();
    if (threadIdx.x == 0) { g_is32 = f; g_acc = 0.0; }
}

// ---------------------------------------------------------------------------
// Convert targets -> uint8 (stays L2-resident for the 19x channel reuse).
// ---------------------------------------------------------------------------
__global__ void prep_kernel(const unsigned int* __restrict__ t) {
    const int n4 = BB * HH * WW / 4;
    const bool is32 = (g_is32 != 0);
    for (int i = blockIdx.x * blockDim.x + threadIdx.x; i < n4;
         i += gridDim.x * blockDim.x) {
        uchar4 o;
        if (is32) {
            uint4 v = reinterpret_cast<const uint4*>(t)[i];
            o.x = (unsigned char)v.x; o.y = (unsigned char)v.y;
            o.z = (unsigned char)v.z; o.w = (unsigned char)v.w;
        } else {
            o.x = (unsigned char)t[(4 * i + 0) * 2];
            o.y = (unsigned char)t[(4 * i + 1) * 2];
            o.z = (unsigned char)t[(4 * i + 2) * 2];
            o.w = (unsigned char)t[(4 * i + 3) * 2];
        }
        reinterpret_cast<uchar4*>(g_tgt8)[i] = o;
    }
}

// ---------------------------------------------------------------------------
// Raw row data (loads only) and derived per-row separable terms.
// ---------------------------------------------------------------------------
struct Raw  { float x0, x1, x2, x3, xl, xr; unsigned t4, tl, tr; };
struct RowD { float a[KX], s[KX], u[KX], v[KX]; };

__device__ __forceinline__ Raw load_row(
    const float* __restrict__ plane, const unsigned char* __restrict__ tplane,
    int row, int ylim, int w0, int lane)
{
    Raw r;
    if ((unsigned)row >= (unsigned)HH || row > ylim) {
        r.x0 = r.x1 = r.x2 = r.x3 = r.xl = r.xr = 0.f;
        r.t4 = 0xFFFFFFFFu; r.tl = 0xFFu; r.tr = 0xFFu;   // 255 != any class -> mask 0
        return r;
    }
    const float* xrow = plane + (size_t)row * WW;
    float4 xv = *reinterpret_cast<const float4*>(xrow + w0);
    float xl  = __shfl_up_sync(0xffffffffu, xv.w, 1);
    float xrt = __shfl_down_sync(0xffffffffu, xv.x, 1);
    if (lane == 0)  xl  = (w0 > 0)       ? __ldg(xrow + w0 - 1)  : 0.f;
    if (lane == 31) xrt = (w0 + KX < WW) ? __ldg(xrow + w0 + KX) : 0.f;
    r.x0 = xv.x; r.x1 = xv.y; r.x2 = xv.z; r.x3 = xv.w; r.xl = xl; r.xr = xrt;

    const unsigned char* trow = tplane + (size_t)row * WW;
    unsigned t4 = *reinterpret_cast<const unsigned*>(trow + w0);
    unsigned tl = __shfl_up_sync(0xffffffffu, t4, 1) >> 24;
    unsigned tr = __shfl_down_sync(0xffffffffu, t4, 1) & 0xFFu;
    if (lane == 0)  tl = (w0 > 0)       ? (unsigned)__ldg(trow + w0 - 1)  : 0xFFu;
    if (lane == 31) tr = (w0 + KX < WW) ? (unsigned)__ldg(trow + w0 + KX) : 0xFFu;
    r.t4 = t4; r.tl = tl; r.tr = tr;
    return r;
}

__device__ __forceinline__ void derive(RowD& d, const Raw& r, unsigned cc) {
    // input: diff-x and smooth-x
    d.a[0] = r.x1 - r.xl;  d.a[1] = r.x2 - r.x0;
    d.a[2] = r.x3 - r.x1;  d.a[3] = r.xr - r.x2;
    d.s[0] = fmaf(2.f, r.x0, r.xl + r.x1);
    d.s[1] = fmaf(2.f, r.x1, r.x0 + r.x2);
    d.s[2] = fmaf(2.f, r.x2, r.x1 + r.x3);
    d.s[3] = fmaf(2.f, r.x3, r.x2 + r.xr);
    // one-hot target masks
    float ml = ( r.tl               == cc) ? 1.f : 0.f;
    float m0 = ((r.t4         & 255u) == cc) ? 1.f : 0.f;
    float m1 = (((r.t4 >> 8)  & 255u) == cc) ? 1.f : 0.f;
    float m2 = (((r.t4 >> 16) & 255u) == cc) ? 1.f : 0.f;
    float m3 = ( (r.t4 >> 24)        == cc) ? 1.f : 0.f;
    float mr = ( r.tr               == cc) ? 1.f : 0.f;
    d.u[0] = m1 - ml; d.u[1] = m2 - m0; d.u[2] = m3 - m1; d.u[3] = mr - m2;
    d.v[0] = fmaf(2.f, m0, ml + m1);
    d.v[1] = fmaf(2.f, m1, m0 + m2);
    d.v[2] = fmaf(2.f, m2, m1 + m3);
    d.v[3] = fmaf(2.f, m3, m2 + mr);
}

__device__ __forceinline__ void emit_row(
    const RowD& P, const RowD& C0, const RowD& N, float& acc)
{
    #pragma unroll
    for (int i = 0; i < KX; i++) {
        float gx  = fmaf(2.f, C0.a[i], P.a[i] + N.a[i]);
        float gy  = N.s[i] - P.s[i];
        float ein = fabsf(gx) + fabsf(gy);
        float gxt = fmaf(2.f, C0.u[i], P.u[i] + N.u[i]);
        float gyt = N.v[i] - P.v[i];
        float etg = fabsf(gxt) + fabsf(gyt);
        float d = ein - etg;
        acc = fmaf(d, d, acc);
    }
}

__global__ __launch_bounds__(WPB * 32, 5)
void edge_kernel(const float* __restrict__ inp)
{
    const int warp = blockIdx.x * WPB + (threadIdx.x >> 5);
    const int lane = threadIdx.x & 31;

    const int wseg = warp & (WSEG - 1);
    const int hch  = (warp >> 2) & (HCH - 1);
    const int t2   = warp >> 5;          // = b*CC + c, in [0, 304)
    const unsigned c = (unsigned)(t2 % CC);
    const int b    = t2 / CC;

    const int w0 = wseg * (32 * KX) + lane * KX;
    const int h0 = hch * HROWS;
    const int ylim = h0 + HROWS;         // deepest row actually needed (halo)
    const float* plane = inp + ((size_t)t2) * HH * WW;
    const unsigned char* tplane = g_tgt8 + (size_t)b * HH * WW;

    float acc = 0.f;
    RowD rA, rB, rC;
    Raw q0, q1, q2;

    // Prologue: fill pipeline, prefetch distance 3.
    q0 = load_row(plane, tplane, h0 - 1, ylim, w0, lane);
    q1 = load_row(plane, tplane, h0,     ylim, w0, lane);
    q2 = load_row(plane, tplane, h0 + 1, ylim, w0, lane);
    derive(rA, q0, c); q0 = load_row(plane, tplane, h0 + 2, ylim, w0, lane);
    derive(rB, q1, c); q1 = load_row(plane, tplane, h0 + 3, ylim, w0, lane);
    // slots now hold: q2=row h0+1, q0=row h0+2, q1=row h0+3

    int y = h0;
    // 21 triples = 63 rows, then 1 remainder (64 total)
    #pragma unroll 1
    for (int it = 0; it < HROWS / 3; ++it) {
        derive(rC, q2, c); emit_row(rA, rB, rC, acc);
        q2 = load_row(plane, tplane, y + 4, ylim, w0, lane); ++y;
        derive(rA, q0, c); emit_row(rB, rC, rA, acc);
        q0 = load_row(plane, tplane, y + 4, ylim, w0, lane); ++y;
        derive(rB, q1, c); emit_row(rC, rA, rB, acc);
        q1 = load_row(plane, tplane, y + 4, ylim, w0, lane); ++y;
    }
    derive(rC, q2, c); emit_row(rA, rB, rC, acc);   // row h0+63

    // reduce: warp -> block -> global double
    #pragma unroll
    for (int o = 16; o; o >>= 1) acc += __shfl_xor_sync(0xffffffffu, acc, o);
    __shared__ float ws[WPB];
    if (lane == 0) ws[threadIdx.x >> 5] = acc;
    __syncthreads();
    if (threadIdx.x == 0) {
        double s = 0.0;
        #pragma unroll
        for (int i = 0; i < WPB; i++) s += (double)ws[i];
        atomicAdd(&g_acc, s);
    }
}

__global__ void fin_kernel(float* __restrict__ out) {
    out[0] = (float)(g_acc * (1.0 / ((double)BB * HH * WW)));
}

// ---------------------------------------------------------------------------
extern "C" void kernel_launch(void* const* d_in, const int* in_sizes, int n_in,
                              void* d_out, int out_size)
{
    const float* inp;
    const unsigned int* tgt;
    if (in_sizes[0] == BB * CC * HH * WW) {
        inp = (const float*)d_in[0];
        tgt = (const unsigned int*)d_in[1];
    } else {
        inp = (const float*)d_in[1];
        tgt = (const unsigned int*)d_in[0];
    }
    float* out = (float*)d_out;

    detect_kernel<<<1, 1024>>>(tgt);
    prep_kernel<<<4096, 256>>>(tgt);
    edge_kernel<<<NBLOCKS, WPB * 32>>>(inp);
    fin_kernel<<<1, 1>>>(out);
}

// round 3
// speedup vs baseline: 2.3069x; 1.6372x over previous
#include <cuda_runtime.h>
#include <stdint.h>

#define BB 16
#define CC 19
#define HH 512
#define WW 512
#define KX 4
#define WSEG 4            // 512 / (32*KX)
#define HCH 8
#define HROWS (HH/HCH)    // 64
#define WPB 4             // warps per block (128 threads)
#define NWARPS (BB*CC*WSEG*HCH)   // 9728
#define NBLOCKS (NWARPS/WPB)      // 2432

__device__ unsigned char g_tgt8[BB*HH*WW];  // 4 MB scratch (static, allowed)
__device__ double g_acc;
__device__ unsigned g_ticket;
__device__ int g_is32;

// ---------------------------------------------------------------------------
// Detect target element width (int64 vs silently-demoted int32); reset acc.
// ---------------------------------------------------------------------------
__global__ void detect_kernel(const unsigned int* __restrict__ t) {
    __shared__ int f;
    if (threadIdx.x == 0) f = 0;
    __syncthreads();
    for (int i = threadIdx.x; i < 4096; i += blockDim.x)
        if (t[2 * i + 1] != 0u) f = 1;
    __syncthreads();
    if (threadIdx.x == 0) { g_is32 = f; g_acc = 0.0; g_ticket = 0u; }
}

// ---------------------------------------------------------------------------
// Convert targets -> uint8 (stays L2-resident for the 19x channel reuse).
// ---------------------------------------------------------------------------
__global__ void prep_kernel(const unsigned int* __restrict__ t) {
    const int n4 = BB * HH * WW / 4;
    const bool is32 = (g_is32 != 0);
    for (int i = blockIdx.x * blockDim.x + threadIdx.x; i < n4;
         i += gridDim.x * blockDim.x) {
        uchar4 o;
        if (is32) {
            uint4 v = reinterpret_cast<const uint4*>(t)[i];
            o.x = (unsigned char)v.x; o.y = (unsigned char)v.y;
            o.z = (unsigned char)v.z; o.w = (unsigned char)v.w;
        } else {
            o.x = (unsigned char)t[(4 * i + 0) * 2];
            o.y = (unsigned char)t[(4 * i + 1) * 2];
            o.z = (unsigned char)t[(4 * i + 2) * 2];
            o.w = (unsigned char)t[(4 * i + 3) * 2];
        }
        reinterpret_cast<uchar4*>(g_tgt8)[i] = o;
    }
}

// ---------------------------------------------------------------------------
// Raw row data (loads only; branch-free halos) and derived separable terms.
// ---------------------------------------------------------------------------
struct Raw  { float x0, x1, x2, x3, xl, xr; unsigned t4, th; };  // th = tl|(tr<<8)
struct RowD { float a[KX], s[KX], u[KX], v[KX]; };

__device__ __forceinline__ float bit2f(unsigned b) {       // b in {0,1} -> 0.f/1.f
    return __int_as_float((int)b * 0x3F800000);
}

__device__ __forceinline__ Raw load_row(
    const float* __restrict__ plane, const unsigned char* __restrict__ tplane,
    int row, int ylim, int w0, int wstart, int lane)
{
    Raw r;
    if ((unsigned)row >= (unsigned)HH || row > ylim) {      // warp-uniform branch
        r.x0 = r.x1 = r.x2 = r.x3 = r.xl = r.xr = 0.f;
        r.t4 = 0xFFFFFFFFu; r.th = 0xFFFFu;                 // 255 != any class
        return r;
    }
    const float* xrow = plane + (size_t)row * WW;
    float4 xv = *reinterpret_cast<const float4*>(xrow + w0);
    // Broadcast halo loads: warp-uniform addresses, unconditional (no divergence).
    const int la = (wstart > 0) ? (wstart - 1) : 0;
    const int ra = (wstart + 128 < WW) ? (wstart + 128) : (WW - 1);
    float hl = __ldg(xrow + la);
    float hr = __ldg(xrow + ra);
    float xsl = __shfl_up_sync(0xffffffffu, xv.w, 1);
    float xsr = __shfl_down_sync(0xffffffffu, xv.x, 1);
    r.xl = (lane == 0)  ? ((wstart > 0)        ? hl : 0.f) : xsl;
    r.xr = (lane == 31) ? ((wstart + 128 < WW) ? hr : 0.f) : xsr;
    r.x0 = xv.x; r.x1 = xv.y; r.x2 = xv.z; r.x3 = xv.w;

    const unsigned char* trow = tplane + (size_t)row * WW;
    unsigned t4 = *reinterpret_cast<const unsigned*>(trow + w0);
    unsigned htl = (unsigned)__ldg(trow + la);              // broadcast
    unsigned htr = (unsigned)__ldg(trow + ra);              // broadcast
    unsigned tsl = __shfl_up_sync(0xffffffffu, t4, 1) >> 24;
    unsigned tsr = __shfl_down_sync(0xffffffffu, t4, 1) & 0xFFu;
    unsigned tl = (lane == 0)  ? ((wstart > 0)        ? htl : 0xFFu) : tsl;
    unsigned tr = (lane == 31) ? ((wstart + 128 < WW) ? htr : 0xFFu) : tsr;
    r.t4 = t4; r.th = tl | (tr << 8);
    return r;
}

__device__ __forceinline__ void derive(RowD& d, const Raw& r, unsigned cc4) {
    // input: diff-x and smooth-x
    d.a[0] = r.x1 - r.xl;  d.a[1] = r.x2 - r.x0;
    d.a[2] = r.x3 - r.x1;  d.a[3] = r.xr - r.x2;
    d.s[0] = fmaf(2.f, r.x0, r.xl + r.x1);
    d.s[1] = fmaf(2.f, r.x1, r.x0 + r.x2);
    d.s[2] = fmaf(2.f, r.x2, r.x1 + r.x3);
    d.s[3] = fmaf(2.f, r.x3, r.x2 + r.xr);
    // one-hot target masks via byte-parallel compare
    unsigned m4 = __vcmpeq4(r.t4, cc4);         // 0xFF per matching byte
    unsigned h2 = __vcmpeq4(r.th, cc4);         // bytes 0 (left), 1 (right)
    float m0 = bit2f( m4         & 1u);
    float m1 = bit2f((m4 >> 8)   & 1u);
    float m2 = bit2f((m4 >> 16)  & 1u);
    float m3 = bit2f((m4 >> 24)  & 1u);
    float ml = bit2f( h2         & 1u);
    float mr = bit2f((h2 >> 8)   & 1u);
    d.u[0] = m1 - ml; d.u[1] = m2 - m0; d.u[2] = m3 - m1; d.u[3] = mr - m2;
    d.v[0] = fmaf(2.f, m0, ml + m1);
    d.v[1] = fmaf(2.f, m1, m0 + m2);
    d.v[2] = fmaf(2.f, m2, m1 + m3);
    d.v[3] = fmaf(2.f, m3, m2 + mr);
}

__device__ __forceinline__ void emit_row(
    const RowD& P, const RowD& C0, const RowD& N, float& acc)
{
    #pragma unroll
    for (int i = 0; i < KX; i++) {
        float gx  = fmaf(2.f, C0.a[i], P.a[i] + N.a[i]);
        float gy  = N.s[i] - P.s[i];
        float ein = fabsf(gx) + fabsf(gy);
        float gxt = fmaf(2.f, C0.u[i], P.u[i] + N.u[i]);
        float gyt = N.v[i] - P.v[i];
        float etg = fabsf(gxt) + fabsf(gyt);
        float d = ein - etg;
        acc = fmaf(d, d, acc);
    }
}

__global__ __launch_bounds__(WPB * 32, 4)
void edge_kernel(const float* __restrict__ inp, float* __restrict__ out)
{
    const int warp = blockIdx.x * WPB + (threadIdx.x >> 5);
    const int lane = threadIdx.x & 31;

    const int wseg = warp & (WSEG - 1);
    const int hch  = (warp >> 2) & (HCH - 1);
    const int t2   = warp >> 5;          // = b*CC + c, in [0, 304)
    const unsigned c = (unsigned)(t2 % CC);
    const int b    = t2 / CC;
    const unsigned cc4 = c * 0x01010101u;

    const int wstart = wseg * (32 * KX);
    const int w0 = wstart + lane * KX;
    const int h0 = hch * HROWS;
    const int ylim = h0 + HROWS;         // deepest input row needed (halo)
    const float* plane = inp + ((size_t)t2) * HH * WW;
    const unsigned char* tplane = g_tgt8 + (size_t)b * HH * WW;

    float acc = 0.f;
    RowD rA, rB, rC;
    Raw q0, q1, q2;

    // Prologue: fill pipeline, prefetch distance 3.
    q0 = load_row(plane, tplane, h0 - 1, ylim, w0, wstart, lane);
    q1 = load_row(plane, tplane, h0,     ylim, w0, wstart, lane);
    q2 = load_row(plane, tplane, h0 + 1, ylim, w0, wstart, lane);
    derive(rA, q0, cc4); q0 = load_row(plane, tplane, h0 + 2, ylim, w0, wstart, lane);
    derive(rB, q1, cc4); q1 = load_row(plane, tplane, h0 + 3, ylim, w0, wstart, lane);

    int y = h0;
    #pragma unroll 1
    for (int it = 0; it < HROWS / 3; ++it) {
        derive(rC, q2, cc4); emit_row(rA, rB, rC, acc);
        q2 = load_row(plane, tplane, y + 4, ylim, w0, wstart, lane); ++y;
        derive(rA, q0, cc4); emit_row(rB, rC, rA, acc);
        q0 = load_row(plane, tplane, y + 4, ylim, w0, wstart, lane); ++y;
        derive(rB, q1, cc4); emit_row(rC, rA, rB, acc);
        q1 = load_row(plane, tplane, y + 4, ylim, w0, wstart, lane); ++y;
    }
    derive(rC, q2, cc4); emit_row(rA, rB, rC, acc);   // row h0+63

    // reduce: warp -> block -> global double; last block finalizes.
    #pragma unroll
    for (int o = 16; o; o >>= 1) acc += __shfl_xor_sync(0xffffffffu, acc, o);
    __shared__ float ws[WPB];
    if (lane == 0) ws[threadIdx.x >> 5] = acc;
    __syncthreads();
    if (threadIdx.x == 0) {
        double s = 0.0;
        #pragma unroll
        for (int i = 0; i < WPB; i++) s += (double)ws[i];
        atomicAdd(&g_acc, s);
        __threadfence();
        unsigned t = atomicAdd(&g_ticket, 1u);
        if (t == (unsigned)(NBLOCKS - 1)) {
            double v = atomicAdd(&g_acc, 0.0);   // ordered read
            out[0] = (float)(v * (1.0 / ((double)BB * HH * WW)));
        }
    }
}

// ---------------------------------------------------------------------------
extern "C" void kernel_launch(void* const* d_in, const int* in_sizes, int n_in,
                              void* d_out, int out_size)
{
    const float* inp;
    const unsigned int* tgt;
    if (in_sizes[0] == BB * CC * HH * WW) {
        inp = (const float*)d_in[0];
        tgt = (const unsigned int*)d_in[1];
    } else {
        inp = (const float*)d_in[1];
        tgt = (const unsigned int*)d_in[0];
    }
    float* out = (float*)d_out;

    detect_kernel<<<1, 1024>>>(tgt);
    prep_kernel<<<4096, 256>>>(tgt);
    edge_kernel<<<NBLOCKS, WPB * 32>>>(inp, out);
}

// round 6
// speedup vs baseline: 3.3000x; 1.4305x over previous
#include <cuda_runtime.h>
#include <stdint.h>

#define BB 16
#define CC 19
#define HH 512
#define WW 512
#define KX 4
#define WSEG 4            // 512 / (32*KX)
#define HCH 8
#define HROWS (HH/HCH)    // 64
#define WPB 4             // warps per block (128 threads)
#define NWARPS (BB*CC*WSEG*HCH)   // 9728
#define NBLOCKS (NWARPS/WPB)      // 2432

#define B01   0x01010101u
#define BIAS4 0x04040404u

__device__ unsigned char g_tgt8[BB*HH*WW];  // 4 MB scratch (static, allowed)
__device__ double g_acc;                     // zero-init; edge's last block re-zeros
__device__ unsigned g_ticket;

// ---------------------------------------------------------------------------
// prep: detect int64-vs-int32 targets and convert to uint8 (L2-resident for
// the 19x channel reuse).
// SAFE sampling: all sampled word indices < 4,194,304 = element count, i.e.
// within the buffer even if the harness allocated int32 (4 bytes/elem).
// With int64, every odd 32-bit word is 0 (labels < 19). With int32, the odd
// words are labels themselves; P(all 16 samples == 0) = 19^-16 ~ 0.
// ---------------------------------------------------------------------------
__global__ void prep_kernel(const unsigned int* __restrict__ t) {
    bool is32 = false;
    #pragma unroll
    for (unsigned k = 0; k < 16; k++) {
        unsigned idx = k * 262139u + 1u;       // odd; max 3,932,086 < 4,194,304
        is32 |= (__ldg(&t[idx | 1u]) != 0u);   // force odd
    }

    const int n4 = BB * HH * WW / 4;
    for (int i = blockIdx.x * blockDim.x + threadIdx.x; i < n4;
         i += gridDim.x * blockDim.x) {
        uchar4 o;
        if (is32) {
            uint4 v = reinterpret_cast<const uint4*>(t)[i];
            o.x = (unsigned char)v.x; o.y = (unsigned char)v.y;
            o.z = (unsigned char)v.z; o.w = (unsigned char)v.w;
        } else {
            o.x = (unsigned char)t[(4 * i + 0) * 2];
            o.y = (unsigned char)t[(4 * i + 1) * 2];
            o.z = (unsigned char)t[(4 * i + 2) * 2];
            o.w = (unsigned char)t[(4 * i + 3) * 2];
        }
        reinterpret_cast<uchar4*>(g_tgt8)[i] = o;
    }
}

// ---------------------------------------------------------------------------
// Raw row (loads only) and derived per-row separable terms.
// Target terms are byte-packed: u biased +1 per byte (in [0,2]), v in [0,4].
// ---------------------------------------------------------------------------
struct Raw  { float x0, x1, x2, x3, xl, xr; unsigned t4, th; };  // th = tl|(tr<<8)
struct RowD { float a[KX], s[KX]; unsigned u, v; };

__device__ __forceinline__ void load_row(
    Raw& r, const float* __restrict__ plane,
    const unsigned char* __restrict__ tplane,
    int row, int w0, int wstart, int lane)
{
    if ((unsigned)row >= (unsigned)HH) {        // warp-uniform
        r.x0 = r.x1 = r.x2 = r.x3 = r.xl = r.xr = 0.f;
        r.t4 = 0xFFFFFFFFu; r.th = 0xFFFFu;     // 255 != any class
        return;
    }
    const float* xrow = plane + (size_t)row * WW;
    float4 xv = *reinterpret_cast<const float4*>(xrow + w0);
    // Warp-uniform broadcast halo loads (no divergence).
    const int la = (wstart > 0) ? (wstart - 1) : 0;
    const int ra = (wstart + 128 < WW) ? (wstart + 128) : (WW - 1);
    float hl = __ldg(xrow + la);
    float hr = __ldg(xrow + ra);
    float xsl = __shfl_up_sync(0xffffffffu, xv.w, 1);
    float xsr = __shfl_down_sync(0xffffffffu, xv.x, 1);
    r.xl = (lane == 0)  ? ((wstart > 0)        ? hl : 0.f) : xsl;
    r.xr = (lane == 31) ? ((wstart + 128 < WW) ? hr : 0.f) : xsr;
    r.x0 = xv.x; r.x1 = xv.y; r.x2 = xv.z; r.x3 = xv.w;

    const unsigned char* trow = tplane + (size_t)row * WW;
    unsigned t4 = *reinterpret_cast<const unsigned*>(trow + w0);
    unsigned htl = (unsigned)__ldg(trow + la);
    unsigned htr = (unsigned)__ldg(trow + ra);
    unsigned tsl = __shfl_up_sync(0xffffffffu, t4, 1) >> 24;
    unsigned tsr = __shfl_down_sync(0xffffffffu, t4, 1) & 0xFFu;
    unsigned tl = (lane == 0)  ? ((wstart > 0)        ? htl : 0xFFu) : tsl;
    unsigned tr = (lane == 31) ? ((wstart + 128 < WW) ? htr : 0xFFu) : tsr;
    r.t4 = t4; r.th = tl | (tr << 8);
}

__device__ __forceinline__ void derive(RowD& d, const Raw& r, unsigned cc4) {
    // input: diff-x / smooth-x
    d.a[0] = r.x1 - r.xl;  d.a[1] = r.x2 - r.x0;
    d.a[2] = r.x3 - r.x1;  d.a[3] = r.xr - r.x2;
    d.s[0] = fmaf(2.f, r.x0, r.xl + r.x1);
    d.s[1] = fmaf(2.f, r.x1, r.x0 + r.x2);
    d.s[2] = fmaf(2.f, r.x2, r.x1 + r.x3);
    d.s[3] = fmaf(2.f, r.x3, r.x2 + r.xr);
    // target: byte-SIMD masks on shifted windows
    unsigned m01  = __vcmpeq4(r.t4, cc4) & B01;
    unsigned l4   = __byte_perm(r.t4, r.th, 0x2104);  // (tl, t0, t1, t2)
    unsigned r4   = __byte_perm(r.t4, r.th, 0x5321);  // (t1, t2, t3, tr)
    unsigned ml01 = __vcmpeq4(l4, cc4) & B01;
    unsigned mr01 = __vcmpeq4(r4, cc4) & B01;
    d.u = (mr01 + B01) - ml01;            // per-byte u+1, in [0,2]; no borrow
    d.v = ml01 + mr01 + (m01 << 1);       // per-byte, in [0,4]; no carry
}

__device__ __forceinline__ float unpack_b(unsigned w, unsigned sel) {
    // byte -> exact float via mantissa insertion; subtract (2^23 + bias 4)
    return __uint_as_float(__byte_perm(w, 0x4B000000u, sel)) - 8388612.0f;
}

__device__ __forceinline__ void emit_row(
    const RowD& P, const RowD& C0, const RowD& N, float& acc)
{
    // packed target gradients, per-byte biased by +4, range [0,8]: carry-free
    unsigned gxt_b = P.u + N.u + (C0.u << 1);
    unsigned gyt_b = (N.v + BIAS4) - P.v;
    #pragma unroll
    for (int i = 0; i < KX; i++) {
        float gx  = fmaf(2.f, C0.a[i], P.a[i] + N.a[i]);
        float gy  = N.s[i] - P.s[i];
        float ein = fabsf(gx) + fabsf(gy);
        unsigned sel = 0x7440u + (unsigned)i;
        float etg = fabsf(unpack_b(gxt_b, sel)) + fabsf(unpack_b(gyt_b, sel));
        float d = ein - etg;
        acc = fmaf(d, d, acc);
    }
}

__global__ __launch_bounds__(WPB * 32, 6)
void edge_kernel(const float* __restrict__ inp, float* __restrict__ out)
{
    const int warp = blockIdx.x * WPB + (threadIdx.x >> 5);
    const int lane = threadIdx.x & 31;

    const int wseg = warp & (WSEG - 1);
    const int hch  = (warp >> 2) & (HCH - 1);
    const int t2   = warp >> 5;               // = b*CC + c, in [0, 304)
    const unsigned c = (unsigned)(t2 % CC);
    const int b    = t2 / CC;
    const unsigned cc4 = c * 0x01010101u;

    const int wstart = wseg * (32 * KX);
    const int w0 = wstart + lane * KX;
    const int h0 = hch * HROWS;
    const float* plane = inp + ((size_t)t2) * HH * WW;
    const unsigned char* tplane = g_tgt8 + (size_t)b * HH * WW;

    float acc = 0.f;
    RowD rA, rB, rC;
    Raw q0, q1;

    // Prologue: invariant at loop top — q0 holds row y+1, q1 holds row y+2.
    load_row(q0, plane, tplane, h0 - 1, w0, wstart, lane);
    load_row(q1, plane, tplane, h0,     w0, wstart, lane);
    derive(rA, q0, cc4); load_row(q0, plane, tplane, h0 + 1, w0, wstart, lane);
    derive(rB, q1, cc4); load_row(q1, plane, tplane, h0 + 2, w0, wstart, lane);

    int y = h0;
    // 6-phase body (LCM of 2 raw slots x 3 row regs), 10 iters = 60 rows
    #pragma unroll 1
    for (int it = 0; it < 10; ++it) {
        derive(rC, q0, cc4); load_row(q0, plane, tplane, y + 3, w0, wstart, lane);
        emit_row(rA, rB, rC, acc); ++y;
        derive(rA, q1, cc4); load_row(q1, plane, tplane, y + 3, w0, wstart, lane);
        emit_row(rB, rC, rA, acc); ++y;
        derive(rB, q0, cc4); load_row(q0, plane, tplane, y + 3, w0, wstart, lane);
        emit_row(rC, rA, rB, acc); ++y;
        derive(rC, q1, cc4); load_row(q1, plane, tplane, y + 3, w0, wstart, lane);
        emit_row(rA, rB, rC, acc); ++y;
        derive(rA, q0, cc4); load_row(q0, plane, tplane, y + 3, w0, wstart, lane);
        emit_row(rB, rC, rA, acc); ++y;
        derive(rB, q1, cc4); load_row(q1, plane, tplane, y + 3, w0, wstart, lane);
        emit_row(rC, rA, rB, acc); ++y;
    }
    // Epilogue: 4 remaining rows (60..63)
    derive(rC, q0, cc4); load_row(q0, plane, tplane, y + 3, w0, wstart, lane);
    emit_row(rA, rB, rC, acc); ++y;
    derive(rA, q1, cc4); load_row(q1, plane, tplane, y + 3, w0, wstart, lane);
    emit_row(rB, rC, rA, acc); ++y;
    derive(rB, q0, cc4); emit_row(rC, rA, rB, acc); ++y;
    derive(rC, q1, cc4); emit_row(rA, rB, rC, acc);

    // reduce: warp -> block -> global double; last block finalizes + resets.
    #pragma unroll
    for (int o = 16; o; o >>= 1) acc += __shfl_xor_sync(0xffffffffu, acc, o);
    __shared__ float ws[WPB];
    if (lane == 0) ws[threadIdx.x >> 5] = acc;
    __syncthreads();
    if (threadIdx.x == 0) {
        double s = 0.0;
        #pragma unroll
        for (int i = 0; i < WPB; i++) s += (double)ws[i];
        atomicAdd(&g_acc, s);
        __threadfence();
        unsigned t = atomicAdd(&g_ticket, 1u);
        if (t == (unsigned)(NBLOCKS - 1)) {
            double v = atomicAdd(&g_acc, 0.0);   // ordered read
            out[0] = (float)(v * (1.0 / ((double)BB * HH * WW)));
            g_acc = 0.0;                          // reset for next replay
            g_ticket = 0u;
        }
    }
}

// ---------------------------------------------------------------------------
extern "C" void kernel_launch(void* const* d_in, const int* in_sizes, int n_in,
                              void* d_out, int out_size)
{
    const float* inp;
    const unsigned int* tgt;
    if (in_sizes[0] == BB * CC * HH * WW) {
        inp = (const float*)d_in[0];
        tgt = (const unsigned int*)d_in[1];
    } else {
        inp = (const float*)d_in[1];
        tgt = (const unsigned int*)d_in[0];
    }
    float* out = (float*)d_out;

    prep_kernel<<<1184, 256>>>(tgt);
    edge_kernel<<<NBLOCKS, WPB * 32>>>(inp, out);
}